// round 5
// baseline (speedup 1.0000x reference)
#include <cuda_runtime.h>
#include <cstdint>

// E=8192 envs, A=128 agents/env, K=512 passengers/env, P=E*K rows x 11 f32 cols.
// Inputs: passengers f32[P,11], accepts/picks bool->32bit [E,A], targets i32[E,A],
//         vectors f32[E,A,4], timesteps i32[E]. Output f32[P,11].

#define NENV   8192
#define NAG    128
#define NPASS  512
#define NTHR   512
#define ROWF   11
#define VEC4S  ((NPASS * ROWF) / 4)   // 1408 float4 per env chunk (22528 B)
#define TAIL   (VEC4S - 2 * NTHR)     // 384

__global__ __launch_bounds__(NTHR, 4)
void pst_kernel(const float* __restrict__ passengers,
                const unsigned int* __restrict__ accepts,
                const unsigned int* __restrict__ picks,
                const int* __restrict__ targets,
                const float* __restrict__ vectors,
                const int* __restrict__ timesteps,
                float* __restrict__ out)
{
    const int e   = blockIdx.x;
    const int tid = threadIdx.x;

    __shared__ int                cnt[NPASS];      // accept multiplicity per local passenger
    __shared__ unsigned char      picked[NPASS];   // zero-dist pick landed on this row
    __shared__ unsigned long long minkey;          // (dist_bits<<32)|agent argmin
    __shared__ float              ts_s;

    // ---------- smem init (NTHR == NPASS: one entry per thread) ----------
    cnt[tid]    = 0;
    picked[tid] = 0;
    if (tid == 0) { ts_s = (float)__ldg(&timesteps[e]); minkey = ~0ull; }

    // ---------- per-agent loads, then front-batched stream loads ----------
    const float INF = __int_as_float(0x7f800000);
    float d  = INF;
    int   lt = 0;
    bool  acc = false, pk = false;
    float4 av;
    if (tid < NAG) {
        av  = reinterpret_cast<const float4*>(vectors)[(size_t)e * NAG + tid];
        lt  = __ldg(&targets[e * NAG + tid]) - e * NPASS;       // local idx in [0,512)
        acc = (accepts[e * NAG + tid] != 0u);                   // robust to i32/f32 widening
        pk  = (picks  [e * NAG + tid] != 0u);
    }

    const float4* __restrict__ src = reinterpret_cast<const float4*>(passengers) + (size_t)e * VEC4S;
    float4*       __restrict__ dst = reinterpret_cast<float4*>(out) + (size_t)e * VEC4S;

    float4 c0 = src[tid];
    float4 c1 = src[tid + NTHR];
    float4 c2;
    if (tid < TAIL) c2 = src[tid + 2 * NTHR];

    // ---------- flag resolution under the load shadow ----------
    if (tid < NAG) {
        float dx = av.x - av.z, dy = av.y - av.w;
        d = sqrtf(dx * dx + dy * dy);
        if (av.x == -100.0f && av.y == -100.0f && av.z == -100.0f && av.w == -100.0f) d = INF;
    }
    __syncthreads();                                            // B1: smem init done

    if (acc) atomicAdd(&cnt[lt], 1);
    if (tid < NAG && pk && d < 1e-6f) picked[lt] = 1;
    __syncthreads();                                            // B2: counts + picked visible

    // dup mask + per-env argmin over where(dup, d, inf).
    // JAX argmin: first index achieving min; all-inf -> index 0. Key bits are
    // monotone in the (nonneg) distance; ties resolve to lowest agent index.
    // The reference while-loop converges in exactly one body call.
    bool dup = acc && (cnt[lt] > 1);
    if (tid < NAG) {
        unsigned long long key =
            ((unsigned long long)__float_as_uint(dup ? d : INF) << 32) | (unsigned)tid;
        #pragma unroll
        for (int s = 16; s > 0; s >>= 1) {
            unsigned long long o = __shfl_down_sync(0xffffffffu, key, s);
            if (o < key) key = o;
        }
        if ((tid & 31) == 0) atomicMin(&minkey, key);
    }
    __syncthreads();                                            // B3: argmin resolved
    const int keep = (int)(minkey & 0xffffffffu);

    // ---------- bulk store ----------
    dst[tid]        = c0;
    dst[tid + NTHR] = c1;
    if (tid < TAIL) dst[tid + 2 * NTHR] = c2;
    __syncthreads();                                            // B4: bulk before patches

    // ---------- agent-driven sparse patches ----------
    // At most one surviving accept agent per row -> unique writer for cols 7/9
    // (and 6 when no pick). Racing pick writers store identical values.
    if (tid < NAG) {
        const float ts = ts_s;
        float* row = reinterpret_cast<float*>(dst) + lt * ROWF;
        bool surviving = acc && !(dup && tid != keep);
        if (surviving) {
            row[7] = (float)tid;
            row[9] = ts;
            if (!picked[lt]) row[6] = 1.0f;
        }
        if (pk && d < 1e-6f) {
            row[6]  = 2.0f;
            row[10] = ts;
        }
    }
}

extern "C" void kernel_launch(void* const* d_in, const int* in_sizes, int n_in,
                              void* d_out, int out_size)
{
    const float*        passengers = (const float*)d_in[0];
    const unsigned int* accepts    = (const unsigned int*)d_in[1];
    const unsigned int* picks      = (const unsigned int*)d_in[2];
    const int*          targets    = (const int*)d_in[3];
    const float*        vectors    = (const float*)d_in[4];
    const int*          timesteps  = (const int*)d_in[5];
    float*              out        = (float*)d_out;

    pst_kernel<<<NENV, NTHR>>>(passengers, accepts, picks, targets, vectors, timesteps, out);
}